// round 6
// baseline (speedup 1.0000x reference)
#include <cuda_runtime.h>

static constexpr int NL  = 4096;     // coarse points
static constexpr int NH  = 16384;    // fine points
static constexpr int NF  = 256;      // features
static constexpr int NC  = 24;       // cells per dim
static constexpr int NC3 = NC*NC*NC; // 13824
static constexpr int PAD = 14336;    // 14*1024 (>= NC3), per-section padded size

static constexpr float DLO  = -4.25f;
static constexpr float DSPAN = 8.5f;
static constexpr float CW   = DSPAN / NC;
static constexpr float CINV = NC / DSPAN;

// ---- scratch (static device globals: no allocation) ----
__device__ int    g_cnt[2*PAD];        // [0,PAD): coarse cells, [PAD,2PAD): fine cells
__device__ int    g_start[2*PAD + 1];  // concatenated exclusive prefix
__device__ int    g_off[2*PAD];        // running scatter cursors
__device__ float4 g_L4[NL];            // cell-sorted (-2lx,-2ly,-2lz,|l|^2)
__device__ int    g_origL[NL];         // sorted pos -> original coarse index
__device__ int    g_permH[NH];         // cell-sorted fine ids
__device__ int    g_topk[3*NH];
__device__ float  g_w[3*NH];

__device__ __forceinline__ int cell1(float v) {
    int i = (int)((v - DLO) * CINV);
    return min(NC - 1, max(0, i));
}

// ---------------- build ----------------
__global__ void k_zero() {
    int i = blockIdx.x * blockDim.x + threadIdx.x;
    if (i < 2*PAD) g_cnt[i] = 0;
}

__global__ void k_count(const float* __restrict__ pl, const float* __restrict__ ph) {
    int i = blockIdx.x * 256 + threadIdx.x;
    if (i < NL) {
        int c = (cell1(pl[3*i]) * NC + cell1(pl[3*i+1])) * NC + cell1(pl[3*i+2]);
        atomicAdd(&g_cnt[c], 1);
    } else if (i < NL + NH) {
        int j = i - NL;
        int c = (cell1(ph[3*j]) * NC + cell1(ph[3*j+1])) * NC + cell1(ph[3*j+2]);
        atomicAdd(&g_cnt[PAD + c], 1);
    }
}

__global__ void k_prefix() {   // one block, 1024 threads; scan 2*PAD = 28672 (chunk 28)
    __shared__ int part[1024];
    const int t = threadIdx.x;
    const int base = t * 28;
    int loc[28];
    int s = 0;
    #pragma unroll
    for (int k = 0; k < 28; ++k) { loc[k] = s; s += g_cnt[base + k]; }
    part[t] = s;
    __syncthreads();
    #pragma unroll
    for (int off = 1; off < 1024; off <<= 1) {
        int v = 0;
        if (t >= off) v = part[t - off];
        __syncthreads();
        if (t >= off) part[t] += v;
        __syncthreads();
    }
    const int pre = (t > 0) ? part[t - 1] : 0;
    #pragma unroll
    for (int k = 0; k < 28; ++k) {
        int v = pre + loc[k];
        g_start[base + k] = v;
        g_off[base + k]   = v;
    }
    if (t == 1023) g_start[2*PAD] = pre + s;   // = NL + NH
}

__global__ void k_scatter(const float* __restrict__ pl, const float* __restrict__ ph) {
    int i = blockIdx.x * 256 + threadIdx.x;
    if (i < NL) {
        const float lx = pl[3*i], ly = pl[3*i+1], lz = pl[3*i+2];
        int c = (cell1(lx) * NC + cell1(ly)) * NC + cell1(lz);
        int pos = atomicAdd(&g_off[c], 1);
        g_L4[pos] = make_float4(-2.0f*lx, -2.0f*ly, -2.0f*lz,
                                fmaf(lx, lx, fmaf(ly, ly, lz*lz)));
        g_origL[pos] = i;
    } else if (i < NL + NH) {
        int j = i - NL;
        int c = (cell1(ph[3*j]) * NC + cell1(ph[3*j+1])) * NC + cell1(ph[3*j+2]);
        int pos = atomicAdd(&g_off[PAD + c], 1) - NL;   // fine section offset by NL
        g_permH[pos] = j;
    }
}

// ---------------- search ----------------
__global__ __launch_bounds__(128)
void k_search(const float* __restrict__ pl, const float* __restrict__ ph) {
    const int t = blockIdx.x * 128 + threadIdx.x;
    const int h = g_permH[t];

    const float hx = ph[3*h], hy = ph[3*h+1], hz = ph[3*h+2];
    const float hh2 = fmaf(hx, hx, fmaf(hy, hy, hz*hz));
    const int ix = cell1(hx), iy = cell1(hy), iz = cell1(hz);

    // top-3 by score = |l|^2 - 2 h.l (identical arithmetic to flat-scan kernel)
    float s0 = 3.4e38f, s1 = 3.4e38f, s2 = 3.4e38f;
    int   i0 = 0, i1 = 0, i2 = 0;

    auto scan = [&](int b, int e) {
        for (int k = b; k < e; ++k) {
            const float4 m = g_L4[k];
            const float s = fmaf(m.x, hx, fmaf(m.y, hy, fmaf(m.z, hz, m.w)));
            if (s < s2) {
                if (s < s1) {
                    s2 = s1; i2 = i1;
                    if (s < s0) { s1 = s0; i1 = i0; s0 = s; i0 = k; }
                    else        { s1 = s;  i1 = k; }
                } else { s2 = s; i2 = k; }
            }
        }
    };

    for (int r = 0; r < NC; ++r) {
        const int xl = max(ix - r, 0), xh = min(ix + r, NC - 1);
        const int yl = max(iy - r, 0), yh = min(iy + r, NC - 1);
        const int zl = max(iz - r, 0), zh = min(iz + r, NC - 1);
        for (int cx = xl; cx <= xh; ++cx) {
            const int adx = abs(cx - ix);
            for (int cy = yl; cy <= yh; ++cy) {
                const int adxy = max(adx, abs(cy - iy));
                const int cbase = (cx * NC + cy) * NC;
                if (adxy == r) {
                    // full z run: cells cbase+zl .. cbase+zh are contiguous in memory
                    scan(g_start[cbase + zl], g_start[cbase + zh + 1]);
                } else {
                    const int czm = iz - r, czp = iz + r;
                    if (czm >= 0)     scan(g_start[cbase + czm], g_start[cbase + czm + 1]);
                    if (czp <= NC-1)  scan(g_start[cbase + czp], g_start[cbase + czp + 1]);
                }
            }
        }
        // rigorous termination: nearest unexplored point is at distance >= D
        float D = 3.4e38f;
        if (ix - r > 0)      D = fminf(D, hx - (DLO + (ix - r) * CW));
        if (ix + r < NC - 1) D = fminf(D, (DLO + (ix + r + 1) * CW) - hx);
        if (iy - r > 0)      D = fminf(D, hy - (DLO + (iy - r) * CW));
        if (iy + r < NC - 1) D = fminf(D, (DLO + (iy + r + 1) * CW) - hy);
        if (iz - r > 0)      D = fminf(D, hz - (DLO + (iz - r) * CW));
        if (iz + r < NC - 1) D = fminf(D, (DLO + (iz + r + 1) * CW) - hz);
        if (s2 < 3.0e38f) {
            const float Dc = fmaxf(D, 0.0f);
            if (Dc * Dc >= s2 + hh2 + 1e-3f) break;   // D=inf (fully explored) also breaks
        }
    }

    // exact squared distances for the 3 selected (matches reference recompute)
    const int a0 = g_origL[i0], a1 = g_origL[i1], a2 = g_origL[i2];
    const int id[3] = {a0, a1, a2};
    float w[3], wsum = 0.0f;
    #pragma unroll
    for (int k = 0; k < 3; ++k) {
        const float lx = pl[3*id[k]+0];
        const float ly = pl[3*id[k]+1];
        const float lz = pl[3*id[k]+2];
        const float dx = hx - lx, dy = hy - ly, dz = hz - lz;
        const float d2 = fmaf(dx, dx, fmaf(dy, dy, dz*dz));
        const float wk = 1.0f / fmaxf(d2, 1e-16f);
        w[k] = wk;
        wsum += wk;
    }
    const float inv = 1.0f / wsum;
    #pragma unroll
    for (int k = 0; k < 3; ++k) {
        g_topk[3*h + k] = id[k];
        g_w[3*h + k]    = w[k] * inv;
    }
}

// ---------------- interpolate ----------------
__global__ __launch_bounds__(256)
void k_interp(const float* __restrict__ x, float* __restrict__ out) {
    const int gw   = (blockIdx.x * 256 + threadIdx.x) >> 5;   // warp per fine point
    const int lane = threadIdx.x & 31;
    const int a = g_topk[3*gw+0], b = g_topk[3*gw+1], c = g_topk[3*gw+2];
    const float w0 = g_w[3*gw+0], w1 = g_w[3*gw+1], w2 = g_w[3*gw+2];

    const float4* __restrict__ x4 = reinterpret_cast<const float4*>(x);
    float4* __restrict__ o4 = reinterpret_cast<float4*>(out);
    const int rowq = NF / 4;   // 64
    const float4* __restrict__ ra = x4 + a * rowq;
    const float4* __restrict__ rb = x4 + b * rowq;
    const float4* __restrict__ rc = x4 + c * rowq;
    float4* __restrict__ ro = o4 + gw * rowq;

    #pragma unroll
    for (int ch = lane; ch < rowq; ch += 32) {
        const float4 va = ra[ch];
        const float4 vb = rb[ch];
        const float4 vc = rc[ch];
        float4 r;
        r.x = fmaf(w2, vc.x, fmaf(w1, vb.x, w0 * va.x));
        r.y = fmaf(w2, vc.y, fmaf(w1, vb.y, w0 * va.y));
        r.z = fmaf(w2, vc.z, fmaf(w1, vb.z, w0 * va.z));
        r.w = fmaf(w2, vc.w, fmaf(w1, vb.w, w0 * va.w));
        ro[ch] = r;
    }
}

extern "C" void kernel_launch(void* const* d_in, const int* in_sizes, int n_in,
                              void* d_out, int out_size) {
    // Map inputs by element count:
    //   x: 4096*256 = 1048576, pos_l: 4096*3 = 12288, pos_h: 16384*3 = 49152
    const float* x     = nullptr;
    const float* pos_l = nullptr;
    const float* pos_h = nullptr;
    for (int i = 0; i < n_in; ++i) {
        if      (in_sizes[i] == NL * NF) x     = (const float*)d_in[i];
        else if (in_sizes[i] == NL * 3)  pos_l = (const float*)d_in[i];
        else if (in_sizes[i] == NH * 3)  pos_h = (const float*)d_in[i];
    }
    float* out = (float*)d_out;

    k_zero   <<<(2*PAD + 1023) / 1024, 1024>>>();
    k_count  <<<(NL + NH) / 256, 256>>>(pos_l, pos_h);
    k_prefix <<<1, 1024>>>();
    k_scatter<<<(NL + NH) / 256, 256>>>(pos_l, pos_h);
    k_search <<<NH / 128, 128>>>(pos_l, pos_h);
    k_interp <<<NH / 8, 256>>>(x, out);
}

// round 7
// speedup vs baseline: 3.5559x; 3.5559x over previous
#include <cuda_runtime.h>

static constexpr int NL   = 4096;    // coarse points
static constexpr int NH   = 16384;   // fine points
static constexpr int NF   = 256;     // features
static constexpr int PPB  = 128;     // fine points per block
static constexpr int SUBS = 8;       // threads cooperating per point
static constexpr int TPB  = PPB * SUBS;   // 1024
static constexpr int HALF = 2048;    // pos_l chunk staged in shared (32 KB as float4)
static constexpr int WIN  = HALF / SUBS;  // 256 candidates per sub per half

__global__ __launch_bounds__(TPB, 1)
void knn_interp_kernel(const float* __restrict__ x,
                       const float* __restrict__ pos_l,
                       const float* __restrict__ pos_h,
                       float* __restrict__ out)
{
    // 32 KB buffer: holds sL during the scan, then is reused (after a barrier)
    // for the per-sub partial top-3 merge arrays (12 KB each).
    __shared__ __align__(16) char smemBuf[HALF * 16];
    __shared__ int   sIdx[PPB][3];
    __shared__ float sW[PPB][3];

    float4* sL  = reinterpret_cast<float4*>(smemBuf);
    float (*sMs)[PPB][3] = reinterpret_cast<float (*)[PPB][3]>(smemBuf);
    int   (*sMi)[PPB][3] = reinterpret_cast<int   (*)[PPB][3]>(smemBuf + SUBS*PPB*3*4);

    const int tid = threadIdx.x;
    const int sub = tid >> 7;          // 0..7 : candidate slice
    const int p   = tid & (PPB - 1);   // 0..127 : fine point within block
    const int h   = blockIdx.x * PPB + p;

    const float hx = pos_h[3*h+0];
    const float hy = pos_h[3*h+1];
    const float hz = pos_h[3*h+2];

    // Partial top-3 by score = |l|^2 - 2 h.l (same ordering as d2 expansion)
    float s0 = 3.4e38f, s1 = 3.4e38f, s2 = 3.4e38f;
    int   i0 = 0, i1 = 0, i2 = 0;

    // sequential insert, identical semantics to the flat-scan R5 kernel
    auto insert = [&](float s, int g) {
        if (s < s1) {
            s2 = s1; i2 = i1;
            if (s < s0) { s1 = s0; i1 = i0; s0 = s; i0 = g; }
            else        { s1 = s;  i1 = g; }
        } else { s2 = s; i2 = g; }
    };

    #pragma unroll 1
    for (int half = 0; half < NL / HALF; ++half) {
        const int base = half * HALF;
        __syncthreads();
        for (int j = tid; j < HALF; j += TPB) {
            const int g = base + j;
            const float lx = pos_l[3*g+0];
            const float ly = pos_l[3*g+1];
            const float lz = pos_l[3*g+2];
            sL[j] = make_float4(-2.0f*lx, -2.0f*ly, -2.0f*lz,
                                fmaf(lx, lx, fmaf(ly, ly, lz*lz)));
        }
        __syncthreads();

        const int jb = sub * WIN;     // all lanes of a warp share jb -> LDS broadcast
        const int gb = base + jb;
        #pragma unroll 4
        for (int jj = 0; jj < WIN; jj += 2) {
            // paired-candidate early reject: one threshold test per 2 candidates
            const float4 ma = sL[jb + jj];
            const float4 mb = sL[jb + jj + 1];
            const float sa = fmaf(ma.x, hx, fmaf(ma.y, hy, fmaf(ma.z, hz, ma.w)));
            const float sb = fmaf(mb.x, hx, fmaf(mb.y, hy, fmaf(mb.z, hz, mb.w)));
            if (fminf(sa, sb) < s2) {
                if (sa < s2) insert(sa, gb + jj);       // a first: preserves
                if (sb < s2) insert(sb, gb + jj + 1);   // sequential order
            }
        }
    }

    __syncthreads();   // all reads of sL done -> safe to alias as merge buffers
    sMs[sub][p][0] = s0; sMs[sub][p][1] = s1; sMs[sub][p][2] = s2;
    sMi[sub][p][0] = i0; sMi[sub][p][1] = i1; sMi[sub][p][2] = i2;
    __syncthreads();

    // Merge 8 partial top-3s -> final top-3; exact-d2 weights.
    // Threads tid<PPB have p==tid, so (hx,hy,hz) already hold this point's coords.
    if (tid < PPB) {
        float b0 = 3.4e38f, b1 = 3.4e38f, b2 = 3.4e38f;
        int   j0 = 0, j1 = 0, j2 = 0;
        #pragma unroll
        for (int ss = 0; ss < SUBS; ++ss) {
            #pragma unroll
            for (int k = 0; k < 3; ++k) {
                const float s = sMs[ss][tid][k];
                const int   g = sMi[ss][tid][k];
                if (s < b2) {
                    if (s < b1) {
                        b2 = b1; j2 = j1;
                        if (s < b0) { b1 = b0; j1 = j0; b0 = s; j0 = g; }
                        else        { b1 = s;  j1 = g; }
                    } else { b2 = s; j2 = g; }
                }
            }
        }
        // Exact squared distances for the 3 selected (matches reference recompute)
        const int id[3] = {j0, j1, j2};
        float w[3];
        float wsum = 0.0f;
        #pragma unroll
        for (int k = 0; k < 3; ++k) {
            const float lx = pos_l[3*id[k]+0];
            const float ly = pos_l[3*id[k]+1];
            const float lz = pos_l[3*id[k]+2];
            const float dx = hx - lx, dy = hy - ly, dz = hz - lz;
            const float d2 = fmaf(dx, dx, fmaf(dy, dy, dz*dz));
            const float wk = 1.0f / fmaxf(d2, 1e-16f);
            w[k] = wk;
            wsum += wk;
        }
        const float inv = 1.0f / wsum;
        sIdx[tid][0] = id[0]; sIdx[tid][1] = id[1]; sIdx[tid][2] = id[2];
        sW[tid][0] = w[0]*inv; sW[tid][1] = w[1]*inv; sW[tid][2] = w[2]*inv;
    }
    __syncthreads();

    // Phase B: gather + weighted sum. One warp per fine point, float4-coalesced.
    const int warp = tid >> 5, lane = tid & 31;   // 32 warps
    const float4* __restrict__ x4 = reinterpret_cast<const float4*>(x);
    float4* __restrict__ o4 = reinterpret_cast<float4*>(out);
    const int rowq = NF / 4;   // 64 float4 per feature row

    for (int pp = warp; pp < PPB; pp += 32) {
        const int hh = blockIdx.x * PPB + pp;
        const int a = sIdx[pp][0], b = sIdx[pp][1], c = sIdx[pp][2];
        const float w0 = sW[pp][0], w1 = sW[pp][1], w2 = sW[pp][2];
        const float4* __restrict__ ra = x4 + a * rowq;
        const float4* __restrict__ rb = x4 + b * rowq;
        const float4* __restrict__ rc = x4 + c * rowq;
        float4* __restrict__ ro = o4 + hh * rowq;
        #pragma unroll
        for (int ch = lane; ch < rowq; ch += 32) {
            const float4 va = ra[ch];
            const float4 vb = rb[ch];
            const float4 vc = rc[ch];
            float4 r;
            r.x = fmaf(w2, vc.x, fmaf(w1, vb.x, w0 * va.x));
            r.y = fmaf(w2, vc.y, fmaf(w1, vb.y, w0 * va.y));
            r.z = fmaf(w2, vc.z, fmaf(w1, vb.z, w0 * va.z));
            r.w = fmaf(w2, vc.w, fmaf(w1, vb.w, w0 * va.w));
            ro[ch] = r;
        }
    }
}

extern "C" void kernel_launch(void* const* d_in, const int* in_sizes, int n_in,
                              void* d_out, int out_size) {
    // Map inputs by element count:
    //   x: 4096*256 = 1048576, pos_l: 4096*3 = 12288, pos_h: 16384*3 = 49152
    const float* x     = nullptr;
    const float* pos_l = nullptr;
    const float* pos_h = nullptr;
    for (int i = 0; i < n_in; ++i) {
        if      (in_sizes[i] == NL * NF) x     = (const float*)d_in[i];
        else if (in_sizes[i] == NL * 3)  pos_l = (const float*)d_in[i];
        else if (in_sizes[i] == NH * 3)  pos_h = (const float*)d_in[i];
    }
    float* out = (float*)d_out;
    knn_interp_kernel<<<NH / PPB, TPB>>>(x, pos_l, pos_h, out);
}

// round 8
// speedup vs baseline: 4.1273x; 1.1607x over previous
#include <cuda_runtime.h>
#include <cstdint>
#include <cstring>

static constexpr int NL   = 4096;    // coarse points
static constexpr int NH   = 16384;   // fine points
static constexpr int NF   = 256;     // features
static constexpr int PPB  = 128;     // fine points per block
static constexpr int SUBS = 8;       // threads cooperating per point
static constexpr int TPB  = PPB * SUBS;   // 1024
static constexpr int HALF = 2048;    // candidates staged per chunk (32 KB packed)
static constexpr int WIN  = HALF / SUBS;  // 256 candidates per sub per chunk
static constexpr int WPAIR = WIN / 2;     // 128 pairs per sub per chunk

// packed f32x2 helpers (sm_103a FFMA2 — PTX-only, see ptx_helpers.cuh pattern)
__device__ __forceinline__ uint64_t ffma2(uint64_t a, uint64_t b, uint64_t c) {
    uint64_t d;
    asm("fma.rn.f32x2 %0, %1, %2, %3;" : "=l"(d) : "l"(a), "l"(b), "l"(c));
    return d;
}
__device__ __forceinline__ uint64_t pack2(float lo, float hi) {
    uint64_t r;
    asm("mov.b64 %0, {%1, %2};" : "=l"(r) : "f"(lo), "f"(hi));
    return r;
}
__device__ __forceinline__ void unpack2(float& lo, float& hi, uint64_t v) {
    asm("mov.b64 {%0, %1}, %2;" : "=f"(lo), "=f"(hi) : "l"(v));
}

__global__ __launch_bounds__(TPB, 1)
void knn_interp_kernel(const float* __restrict__ x,
                       const float* __restrict__ pos_l,
                       const float* __restrict__ pos_h,
                       float* __restrict__ out)
{
    // 32 KB buffer: pair-packed candidate table during the scan, then reused
    // (after a barrier) for the per-sub partial top-3 merge arrays (24 KB).
    __shared__ __align__(16) char smemBuf[HALF * 16];
    __shared__ int   sIdx[PPB][3];
    __shared__ float sW[PPB][3];

    // QA[j] = (xpair, ypair), QB[j] = (zpair, wpair); x=-2lx etc., w=|l|^2
    ulonglong2* sQA = reinterpret_cast<ulonglong2*>(smemBuf);            // 16 KB
    ulonglong2* sQB = reinterpret_cast<ulonglong2*>(smemBuf + HALF*8);   // 16 KB
    float (*sMs)[PPB][3] = reinterpret_cast<float (*)[PPB][3]>(smemBuf);
    int   (*sMi)[PPB][3] = reinterpret_cast<int   (*)[PPB][3]>(smemBuf + SUBS*PPB*3*4);

    const int tid = threadIdx.x;
    const int sub = tid >> 7;          // 0..7 : candidate slice
    const int p   = tid & (PPB - 1);   // 0..127 : fine point within block
    const int h   = blockIdx.x * PPB + p;

    const float hx = pos_h[3*h+0];
    const float hy = pos_h[3*h+1];
    const float hz = pos_h[3*h+2];
    const uint64_t hx2 = pack2(hx, hx);
    const uint64_t hy2 = pack2(hy, hy);
    const uint64_t hz2 = pack2(hz, hz);

    // Partial top-3 by score = |l|^2 - 2 h.l (bit-identical to flat-scan R5)
    float s0 = 3.4e38f, s1 = 3.4e38f, s2 = 3.4e38f;
    int   i0 = 0, i1 = 0, i2 = 0;

    auto insert = [&](float s, int g) {   // same nested form as R5 (proven codegen)
        if (s < s1) {
            s2 = s1; i2 = i1;
            if (s < s0) { s1 = s0; i1 = i0; s0 = s; i0 = g; }
            else        { s1 = s;  i1 = g; }
        } else { s2 = s; i2 = g; }
    };

    #pragma unroll 1
    for (int half = 0; half < NL / HALF; ++half) {
        const int base = half * HALF;
        __syncthreads();
        // stage: one candidate-pair per thread (HALF/2 == TPB)
        {
            const int pj = tid;
            const int g  = base + 2*pj;
            const float ax = pos_l[3*g+0], ay = pos_l[3*g+1], az = pos_l[3*g+2];
            const float bx = pos_l[3*g+3], by = pos_l[3*g+4], bz = pos_l[3*g+5];
            const float wa = fmaf(ax, ax, fmaf(ay, ay, az*az));
            const float wb = fmaf(bx, bx, fmaf(by, by, bz*bz));
            sQA[pj] = make_ulonglong2(pack2(-2.0f*ax, -2.0f*bx),
                                      pack2(-2.0f*ay, -2.0f*by));
            sQB[pj] = make_ulonglong2(pack2(-2.0f*az, -2.0f*bz),
                                      pack2(wa, wb));
        }
        __syncthreads();

        const int pb = sub * WPAIR;            // warp-uniform -> LDS broadcast
        const int gb = base + 2*pb;
        #pragma unroll 8
        for (int jp = 0; jp < WPAIR; ++jp) {
            const ulonglong2 qa = sQA[pb + jp];   // (xpair, ypair)
            const ulonglong2 qb = sQB[pb + jp];   // (zpair, wpair)
            uint64_t t = ffma2(qb.x, hz2, qb.y);
            t = ffma2(qa.y, hy2, t);
            t = ffma2(qa.x, hx2, t);
            float sa, sb;
            unpack2(sa, sb, t);
            const int g = gb + 2*jp;
            if (sa < s2) insert(sa, g);       // sequential order preserved:
            if (sb < s2) insert(sb, g + 1);   // a first, then b
        }
    }

    __syncthreads();   // all reads of sQA/sQB done -> safe to alias as merge buffers
    sMs[sub][p][0] = s0; sMs[sub][p][1] = s1; sMs[sub][p][2] = s2;
    sMi[sub][p][0] = i0; sMi[sub][p][1] = i1; sMi[sub][p][2] = i2;
    __syncthreads();

    // Merge 8 partial top-3s -> final top-3; exact-d2 weights.
    // Threads tid<PPB have p==tid, so (hx,hy,hz) already hold this point's coords.
    if (tid < PPB) {
        float b0 = 3.4e38f, b1 = 3.4e38f, b2 = 3.4e38f;
        int   j0 = 0, j1 = 0, j2 = 0;
        #pragma unroll
        for (int ss = 0; ss < SUBS; ++ss) {
            #pragma unroll
            for (int k = 0; k < 3; ++k) {
                const float s = sMs[ss][tid][k];
                const int   g = sMi[ss][tid][k];
                if (s < b2) {
                    if (s < b1) {
                        b2 = b1; j2 = j1;
                        if (s < b0) { b1 = b0; j1 = j0; b0 = s; j0 = g; }
                        else        { b1 = s;  j1 = g; }
                    } else { b2 = s; j2 = g; }
                }
            }
        }
        // Exact squared distances for the 3 selected (matches reference recompute)
        const int id[3] = {j0, j1, j2};
        float w[3];
        float wsum = 0.0f;
        #pragma unroll
        for (int k = 0; k < 3; ++k) {
            const float lx = pos_l[3*id[k]+0];
            const float ly = pos_l[3*id[k]+1];
            const float lz = pos_l[3*id[k]+2];
            const float dx = hx - lx, dy = hy - ly, dz = hz - lz;
            const float d2 = fmaf(dx, dx, fmaf(dy, dy, dz*dz));
            const float wk = 1.0f / fmaxf(d2, 1e-16f);
            w[k] = wk;
            wsum += wk;
        }
        const float inv = 1.0f / wsum;
        sIdx[tid][0] = id[0]; sIdx[tid][1] = id[1]; sIdx[tid][2] = id[2];
        sW[tid][0] = w[0]*inv; sW[tid][1] = w[1]*inv; sW[tid][2] = w[2]*inv;
    }
    __syncthreads();

    // Phase B: gather + weighted sum. One warp per fine point, float4-coalesced.
    const int warp = tid >> 5, lane = tid & 31;   // 32 warps
    const float4* __restrict__ x4 = reinterpret_cast<const float4*>(x);
    float4* __restrict__ o4 = reinterpret_cast<float4*>(out);
    const int rowq = NF / 4;   // 64 float4 per feature row

    for (int pp = warp; pp < PPB; pp += 32) {
        const int hh = blockIdx.x * PPB + pp;
        const int a = sIdx[pp][0], b = sIdx[pp][1], c = sIdx[pp][2];
        const float w0 = sW[pp][0], w1 = sW[pp][1], w2 = sW[pp][2];
        const float4* __restrict__ ra = x4 + a * rowq;
        const float4* __restrict__ rb = x4 + b * rowq;
        const float4* __restrict__ rc = x4 + c * rowq;
        float4* __restrict__ ro = o4 + hh * rowq;
        #pragma unroll
        for (int ch = lane; ch < rowq; ch += 32) {
            const float4 va = ra[ch];
            const float4 vb = rb[ch];
            const float4 vc = rc[ch];
            float4 r;
            r.x = fmaf(w2, vc.x, fmaf(w1, vb.x, w0 * va.x));
            r.y = fmaf(w2, vc.y, fmaf(w1, vb.y, w0 * va.y));
            r.z = fmaf(w2, vc.z, fmaf(w1, vb.z, w0 * va.z));
            r.w = fmaf(w2, vc.w, fmaf(w1, vb.w, w0 * va.w));
            ro[ch] = r;
        }
    }
}

extern "C" void kernel_launch(void* const* d_in, const int* in_sizes, int n_in,
                              void* d_out, int out_size) {
    // Map inputs by element count:
    //   x: 4096*256 = 1048576, pos_l: 4096*3 = 12288, pos_h: 16384*3 = 49152
    const float* x     = nullptr;
    const float* pos_l = nullptr;
    const float* pos_h = nullptr;
    for (int i = 0; i < n_in; ++i) {
        if      (in_sizes[i] == NL * NF) x     = (const float*)d_in[i];
        else if (in_sizes[i] == NL * 3)  pos_l = (const float*)d_in[i];
        else if (in_sizes[i] == NH * 3)  pos_h = (const float*)d_in[i];
    }
    float* out = (float*)d_out;
    knn_interp_kernel<<<NH / PPB, TPB>>>(x, pos_l, pos_h, out);
}